// round 13
// baseline (speedup 1.0000x reference)
#include <cuda_runtime.h>
#include <cuda_fp16.h>
#include <math.h>

// Problem constants
#define BB 2
#define VV 180
#define RR 32
#define CC 512
#define NPIX 512
#define NROWS (BB*VV*RR)        // 11520
#define NQUADS (NROWS/4)        // 2880
#define NPAIRS (NROWS/2)        // 5760
#define PADL 107
#define NPADE 724               // padded entries per row
#define PI_D 3.14159265358979323846
#define MAGICF 12582912.0f      // 1.5*2^23
#define KCONST 362.0f           // 255.5 + PADL - 0.5
#define BUFB2 (NPADE * 8)       // bytes per pair-row buffer (5792)

// ---------------- device globals (scratch; no runtime allocation allowed) ----------------
// pair-interleaved padded rows: 8B entry = (half2(mid_r0,mid_r1), half2(d_r0,d_r1))
__device__ __align__(16) uint2 g_pair[(size_t)NPAIRS * NPADE];   // ~33MB

// ---------------- filter: closed-form Ram-Lak, parity-split conv, 8-wide blocking ------
__global__ void __launch_bounds__(256) filter_kernel(const float* __restrict__ sino) {
    __shared__ __align__(16) float sE[4][512];
    __shared__ __align__(16) float sO[4][512];
    __shared__ __align__(16) float sh[256];
    __shared__ __align__(16) float sF[4][512];

    int quad = blockIdx.x;
    int tid  = threadIdx.x;

    for (int i = tid; i < 512; i += 256) {
        int g  = i >> 7;
        int lt = i & 127;
        const float4* rp = (const float4*)(sino + (size_t)(quad * 4 + g) * CC);
        float4 rv = rp[lt];
        int e0i = lt * 2;
        *(float2*)&sE[g][e0i]       = make_float2(rv.x, rv.z);
        *(float2*)&sE[g][e0i + 256] = make_float2(rv.x, rv.z);
        *(float2*)&sO[g][e0i]       = make_float2(rv.y, rv.w);
        *(float2*)&sO[g][e0i + 256] = make_float2(rv.y, rv.w);
    }
    {
        float s = sinf((float)(2 * tid + 1) * (float)(PI_D / 512.0));
        sh[tid] = -7.62939453125e-6f / (s * s);    // -(2/512^2)/sin^2
    }
    __syncthreads();

    int g  = tid >> 6;
    int p  = (tid >> 5) & 1;
    int q  = tid & 31;
    int o0 = q * 8;

    const float* part = p ? sE[g] : sO[g];
    const float* own  = p ? sO[g] : sE[g];

    float a0=0.f,a1=0.f,a2=0.f,a3=0.f,a4=0.f,a5=0.f,a6=0.f,a7=0.f;
    float4 B4 = *(const float4*)&part[o0 + 256];
    float4 C4 = *(const float4*)&part[o0 + 260];
    if (p == 0) {
        #pragma unroll 4
        for (int k0 = 0; k0 < 256; k0 += 4) {
            float4 hv = *(const float4*)&sh[k0];
            float4 A4 = *(const float4*)&part[o0 - k0 + 252];
            a0 = fmaf(hv.x, A4.w, a0); a0 = fmaf(hv.y, A4.z, a0); a0 = fmaf(hv.z, A4.y, a0); a0 = fmaf(hv.w, A4.x, a0);
            a1 = fmaf(hv.x, B4.x, a1); a1 = fmaf(hv.y, A4.w, a1); a1 = fmaf(hv.z, A4.z, a1); a1 = fmaf(hv.w, A4.y, a1);
            a2 = fmaf(hv.x, B4.y, a2); a2 = fmaf(hv.y, B4.x, a2); a2 = fmaf(hv.z, A4.w, a2); a2 = fmaf(hv.w, A4.z, a2);
            a3 = fmaf(hv.x, B4.z, a3); a3 = fmaf(hv.y, B4.y, a3); a3 = fmaf(hv.z, B4.x, a3); a3 = fmaf(hv.w, A4.w, a3);
            a4 = fmaf(hv.x, B4.w, a4); a4 = fmaf(hv.y, B4.z, a4); a4 = fmaf(hv.z, B4.y, a4); a4 = fmaf(hv.w, B4.x, a4);
            a5 = fmaf(hv.x, C4.x, a5); a5 = fmaf(hv.y, B4.w, a5); a5 = fmaf(hv.z, B4.z, a5); a5 = fmaf(hv.w, B4.y, a5);
            a6 = fmaf(hv.x, C4.y, a6); a6 = fmaf(hv.y, C4.x, a6); a6 = fmaf(hv.z, B4.w, a6); a6 = fmaf(hv.w, B4.z, a6);
            a7 = fmaf(hv.x, C4.z, a7); a7 = fmaf(hv.y, C4.y, a7); a7 = fmaf(hv.z, C4.x, a7); a7 = fmaf(hv.w, B4.w, a7);
            C4 = B4; B4 = A4;
        }
    } else {
        #pragma unroll 4
        for (int k0 = 0; k0 < 256; k0 += 4) {
            float4 hv = *(const float4*)&sh[k0];
            float4 A4 = *(const float4*)&part[o0 - k0 + 252];
            a0 = fmaf(hv.x, B4.x, a0); a0 = fmaf(hv.y, A4.w, a0); a0 = fmaf(hv.z, A4.z, a0); a0 = fmaf(hv.w, A4.y, a0);
            a1 = fmaf(hv.x, B4.y, a1); a1 = fmaf(hv.y, B4.x, a1); a1 = fmaf(hv.z, A4.w, a1); a1 = fmaf(hv.w, A4.z, a1);
            a2 = fmaf(hv.x, B4.z, a2); a2 = fmaf(hv.y, B4.y, a2); a2 = fmaf(hv.z, B4.x, a2); a2 = fmaf(hv.w, A4.w, a2);
            a3 = fmaf(hv.x, B4.w, a3); a3 = fmaf(hv.y, B4.z, a3); a3 = fmaf(hv.z, B4.y, a3); a3 = fmaf(hv.w, B4.x, a3);
            a4 = fmaf(hv.x, C4.x, a4); a4 = fmaf(hv.y, B4.w, a4); a4 = fmaf(hv.z, B4.z, a4); a4 = fmaf(hv.w, B4.y, a4);
            a5 = fmaf(hv.x, C4.y, a5); a5 = fmaf(hv.y, C4.x, a5); a5 = fmaf(hv.z, B4.w, a5); a5 = fmaf(hv.w, B4.z, a5);
            a6 = fmaf(hv.x, C4.z, a6); a6 = fmaf(hv.y, C4.y, a6); a6 = fmaf(hv.z, C4.x, a6); a6 = fmaf(hv.w, B4.w, a6);
            a7 = fmaf(hv.x, C4.w, a7); a7 = fmaf(hv.y, C4.z, a7); a7 = fmaf(hv.z, C4.y, a7); a7 = fmaf(hv.w, C4.x, a7);
            C4 = B4; B4 = A4;
        }
    }
    int ob = 2 * o0 + p;
    sF[g][ob + 0]  = fmaf(0.5f, own[o0 + 0], a0);
    sF[g][ob + 2]  = fmaf(0.5f, own[o0 + 1], a1);
    sF[g][ob + 4]  = fmaf(0.5f, own[o0 + 2], a2);
    sF[g][ob + 6]  = fmaf(0.5f, own[o0 + 3], a3);
    sF[g][ob + 8]  = fmaf(0.5f, own[o0 + 4], a4);
    sF[g][ob + 10] = fmaf(0.5f, own[o0 + 5], a5);
    sF[g][ob + 12] = fmaf(0.5f, own[o0 + 6], a6);
    sF[g][ob + 14] = fmaf(0.5f, own[o0 + 7], a7);
    __syncthreads();

    // pack: pair-entry[j] = (half2(mid_r0,mid_r1), half2(d_r0,d_r1)); two pair-rows/quad
    uint2* dst0 = g_pair + (size_t)(quad * 2) * NPADE;
    for (int j = tid; j < NPADE; j += 256) {
        int ia = j - PADL;       ia = ia < 0 ? 0 : (ia > 511 ? 511 : ia);
        int ib = j - (PADL - 1); ib = ib < 0 ? 0 : (ib > 511 ? 511 : ib);
        float f0a = sF[0][ia], f0b = sF[0][ib];
        float f1a = sF[1][ia], f1b = sF[1][ib];
        float f2a = sF[2][ia], f2b = sF[2][ib];
        float f3a = sF[3][ia], f3b = sF[3][ib];
        __half2 m01 = __floats2half2_rn(0.5f * (f0a + f0b), 0.5f * (f1a + f1b));
        __half2 d01 = __floats2half2_rn(f0b - f0a, f1b - f1a);
        __half2 m23 = __floats2half2_rn(0.5f * (f2a + f2b), 0.5f * (f3a + f3b));
        __half2 d23 = __floats2half2_rn(f2b - f2a, f3b - f3a);
        uint2 e0, e1;
        e0.x = *(unsigned int*)&m01; e0.y = *(unsigned int*)&d01;
        e1.x = *(unsigned int*)&m23; e1.y = *(unsigned int*)&d23;
        dst0[j]         = e0;
        dst0[NPADE + j] = e1;
    }
}

// ---------------- cp.async helpers ------------------------------------------------------
__device__ __forceinline__ void cp16(unsigned int sdst, const void* gsrc) {
    asm volatile("cp.async.cg.shared.global [%0], [%1], 16;" :: "r"(sdst), "l"(gsrc));
}
__device__ __forceinline__ void cp_commit() { asm volatile("cp.async.commit_group;"); }
__device__ __forceinline__ void cp_wait1()  { asm volatile("cp.async.wait_group 1;"); }
__device__ __forceinline__ void cp_wait0()  { asm volatile("cp.async.wait_group 0;"); }

// ---------------- backprojection: mirror-angle sharing, r-pair x 16-y tiles -------------
// 1024 blocks x 512 threads. Block = (b, r-pair rp, 16-y slab).
// tid = jh*256 + xh: pixel pair (xh, 511-xh), jh selects 8-y half; 8 j each.
// Groups g=0..88: rows v=g+1, vm=179-g; t_vm(x)=t_v(-x). 8B entries -> LDS.64 gathers.
__global__ void __launch_bounds__(512, 2) bp_kernel(float* __restrict__ out) {
    __shared__ __align__(16) uint2 sbuf[4][NPADE];   // 4 pair-row buffers, 23.2KB
    __shared__ float2 scs[90];

    int tid  = threadIdx.x;
    int blk  = blockIdx.x;
    int slab = blk & 31;              // 32 slabs of 16 y
    int rp   = (blk >> 5) & 15;       // 16 r-pairs
    int b    = blk >> 9;

    if (tid < 90) {
        float th = (float)((double)tid * (PI_D / (double)VV));
        float s, c;
        sincosf(th, &s, &c);
        scs[tid] = make_float2(c, s);
    }

    int xh = tid & 255;
    int jh = tid >> 8;

    unsigned int sb32;
    asm("{ .reg .u64 t; cvta.to.shared.u64 t, %1; cvt.u32.u64 %0, t; }"
        : "=r"(sb32) : "l"((void*)&sbuf[0][0]));
    unsigned int cb = sb32 - 0x5A000000u;  // addr = bits(ts)*8 + cb + buf*BUFB2

    // pair-row base for (b, v, rp); per-angle stride = 16 pair-rows = 5792 uint4
    const uint4* gq4 = (const uint4*)(g_pair + ((size_t)(b * VV) * 16 + rp) * NPADE);
    const size_t vstr = (size_t)16 * NPADE / 2;   // uint4 per angle step (5792)

    // stage pair-rows of angles (vA, vB) into buffer pair p (bufs 2p, 2p+1)
    auto stage = [&](int vA, int vB, int p) {
        const uint4* sA = gq4 + (size_t)vA * vstr;
        const uint4* sB = gq4 + (size_t)vB * vstr;
        unsigned int base = sb32 + (unsigned int)(2 * p) * BUFB2;
        if (tid < 362) cp16(base + tid * 16u, sA + tid);
        else           cp16(base + BUFB2 + (tid - 362) * 16u, sB + (tid - 362));
        if (tid < 212) cp16(base + BUFB2 + (tid + 150) * 16u, sB + tid + 150);
    };

    // prologue: group0 (v=1,179) -> pair0 ; group1 (v=2,178) -> pair1
    stage(1, 179, 0); cp_commit();
    stage(2, 178, 1); cp_commit();

    float xp = (float)xh - 255.5f;
    float yb = (float)(slab * 16 + jh * 8) - 255.5f;

    float accA[2][8], accB[2][8];     // [r][j]
    #pragma unroll
    for (int r = 0; r < 2; r++)
        #pragma unroll
        for (int j = 0; j < 8; j++) { accA[r][j] = 0.f; accB[r][j] = 0.f; }

    __half2 hA[8], hB[8];
    #pragma unroll
    for (int j = 0; j < 8; j++) { hA[j] = __float2half2_rn(0.f); hB[j] = __float2half2_rn(0.f); }

    for (int g = 0; g < 89; g++) {
        cp_wait1();
        __syncthreads();

        int p = g & 1;
        unsigned int cbV = cb + (unsigned int)(2 * p) * BUFB2;
        float2 cs = scs[g + 1];
        float u   = xp * cs.x;
        float w00 = fmaf(yb, cs.y, KCONST);
        float tA0 = __fadd_rn(w00, u);
        float tB0 = __fadd_rn(w00, -u);

        #pragma unroll
        for (int j = 0; j < 8; j++) {
            float tA = fmaf((float)j, cs.y, tA0);
            float tB = fmaf((float)j, cs.y, tB0);
            float tsA  = __fadd_rn(tA, MAGICF);
            float i0A  = __fadd_rn(tsA, -MAGICF);
            float wA   = __fadd_rn(tA, -i0A);
            float tsB  = __fadd_rn(tB, MAGICF);
            float i0B  = __fadd_rn(tsB, -MAGICF);
            float wB   = __fadd_rn(tB, -i0B);
            unsigned int uA = __float_as_uint(tsA) * 8u + cbV;
            unsigned int uB = __float_as_uint(tsB) * 8u + cbV;
            unsigned int wAb, wBb;
            asm("cvt.rn.f16x2.f32 %0, %1, %1;" : "=r"(wAb) : "f"(wA));
            asm("cvt.rn.f16x2.f32 %0, %1, %1;" : "=r"(wBb) : "f"(wB));
            __half2 wA2 = *(__half2*)&wAb, wB2 = *(__half2*)&wBb;

            unsigned int m, d;
            // row V @ A
            asm("ld.shared.v2.b32 {%0,%1}, [%2];" : "=r"(m), "=r"(d) : "r"(uA));
            hA[j] = __hadd2(hA[j], __hfma2(wA2, *(__half2*)&d, *(__half2*)&m));
            // row V @ B
            asm("ld.shared.v2.b32 {%0,%1}, [%2];" : "=r"(m), "=r"(d) : "r"(uB));
            hB[j] = __hadd2(hB[j], __hfma2(wB2, *(__half2*)&d, *(__half2*)&m));
            // row VM @ B -> pixel A (immediate +BUFB2)
            asm("ld.shared.v2.b32 {%0,%1}, [%2+5792];" : "=r"(m), "=r"(d) : "r"(uB));
            hA[j] = __hadd2(hA[j], __hfma2(wB2, *(__half2*)&d, *(__half2*)&m));
            // row VM @ A -> pixel B
            asm("ld.shared.v2.b32 {%0,%1}, [%2+5792];" : "=r"(m), "=r"(d) : "r"(uA));
            hB[j] = __hadd2(hB[j], __hfma2(wA2, *(__half2*)&d, *(__half2*)&m));
        }

        __syncthreads();
        // stage group g+2 into pair g&1 (v = g+3, 177-g); group 89 = specials (0, 90)
        if (g + 2 <= 88)      stage(g + 3, 177 - g, p);
        else if (g + 2 == 89) stage(0, 90, p);
        cp_commit();

        // flush chunk every 4 groups (8 half-adds per acc)
        if ((g & 3) == 3) {
            #pragma unroll
            for (int j = 0; j < 8; j++) {
                accA[0][j] += __low2float(hA[j]);  accA[1][j] += __high2float(hA[j]);
                accB[0][j] += __low2float(hB[j]);  accB[1][j] += __high2float(hB[j]);
                hA[j] = __float2half2_rn(0.f);     hB[j] = __float2half2_rn(0.f);
            }
        }
    }

    // epilogue: specials v=0 (buf2) and v=90 (buf3), staged into pair 1 at g=87
    cp_wait0();
    __syncthreads();
    {
        unsigned int cb0 = cb + 2u * BUFB2;
        // v=0: t' = +-xp + K, y-independent
        {
            float tA = __fadd_rn(KCONST, xp);
            float tsA = __fadd_rn(tA, MAGICF);
            float wA  = __fadd_rn(tA, -__fadd_rn(tsA, -MAGICF));
            float tB = __fadd_rn(KCONST, -xp);
            float tsB = __fadd_rn(tB, MAGICF);
            float wB  = __fadd_rn(tB, -__fadd_rn(tsB, -MAGICF));
            unsigned int wAb, wBb;
            asm("cvt.rn.f16x2.f32 %0, %1, %1;" : "=r"(wAb) : "f"(wA));
            asm("cvt.rn.f16x2.f32 %0, %1, %1;" : "=r"(wBb) : "f"(wB));
            unsigned int m, d;
            asm("ld.shared.v2.b32 {%0,%1}, [%2];"
                : "=r"(m), "=r"(d) : "r"(__float_as_uint(tsA) * 8u + cb0));
            __half2 vA2 = __hfma2(*(__half2*)&wAb, *(__half2*)&d, *(__half2*)&m);
            asm("ld.shared.v2.b32 {%0,%1}, [%2];"
                : "=r"(m), "=r"(d) : "r"(__float_as_uint(tsB) * 8u + cb0));
            __half2 vB2 = __hfma2(*(__half2*)&wBb, *(__half2*)&d, *(__half2*)&m);
            #pragma unroll
            for (int j = 0; j < 8; j++) {
                hA[j] = __hadd2(hA[j], vA2);
                hB[j] = __hadd2(hB[j], vB2);
            }
        }
        // v=90: t' = yb + j + K, x-independent -> same contribution to A and B
        #pragma unroll
        for (int j = 0; j < 8; j++) {
            float t  = __fadd_rn(__fadd_rn(yb, (float)j), KCONST);
            float ts = __fadd_rn(t, MAGICF);
            float w  = __fadd_rn(t, -__fadd_rn(ts, -MAGICF));
            unsigned int wb;
            asm("cvt.rn.f16x2.f32 %0, %1, %1;" : "=r"(wb) : "f"(w));
            unsigned int m, d;
            asm("ld.shared.v2.b32 {%0,%1}, [%2+5792];"
                : "=r"(m), "=r"(d) : "r"(__float_as_uint(ts) * 8u + cb0));
            __half2 v2 = __hfma2(*(__half2*)&wb, *(__half2*)&d, *(__half2*)&m);
            hA[j] = __hadd2(hA[j], v2);
            hB[j] = __hadd2(hB[j], v2);
        }
        // final flush
        #pragma unroll
        for (int j = 0; j < 8; j++) {
            accA[0][j] += __low2float(hA[j]);  accA[1][j] += __high2float(hA[j]);
            accB[0][j] += __low2float(hB[j]);  accB[1][j] += __high2float(hB[j]);
        }
    }

    const float scale = (float)(PI_D / (double)VV);
    int y0 = slab * 16 + jh * 8;
    #pragma unroll
    for (int r = 0; r < 2; r++) {
        size_t obase = (((size_t)(b * RR + rp * 2 + r)) * NPIX + y0) * NPIX;
        #pragma unroll
        for (int j = 0; j < 8; j++) {
            float vA = accA[r][j] * scale;
            float vB = accB[r][j] * scale;
            out[obase + (size_t)j * NPIX + xh]         = vA > 0.f ? vA : 0.f;
            out[obase + (size_t)j * NPIX + (511 - xh)] = vB > 0.f ? vB : 0.f;
        }
    }
}

// ---------------- launch ----------------------------------------------------------------
extern "C" void kernel_launch(void* const* d_in, const int* in_sizes, int n_in,
                              void* d_out, int out_size) {
    const float* sino = (const float*)d_in[0];
    float* out = (float*)d_out;
    (void)in_sizes; (void)n_in; (void)out_size;

    filter_kernel<<<NQUADS, 256>>>(sino);
    bp_kernel<<<BB * 16 * 32, 512>>>(out);
}